// round 2
// baseline (speedup 1.0000x reference)
#include <cuda_runtime.h>

// Problem constants
#define NV_    4096   // concept embeddings
#define B_     8      // batch
#define ND_    512    // tokens per batch row
#define NODES_ 512    // phi_vs node_num
#define D_     128    // embedding dim (= GEMM K)

// f32 bin geometry, matching jnp.linspace(-0.5, 0.99, 15) computed in f32
#define STEPF    ((0.99f - (-0.5f)) / 14.0f)
#define INV_STEP 9.3959731543624161f          // 14/1.49 (double, rounded)
#define HALF_INV_STEP 4.6979865771812080f     // 0.5 * INV_STEP

typedef unsigned long long u64;

// Per-row-block partial sums: 32 row-blocks x 4096 concepts. No atomics, no
// zero-init needed (every slot is written exactly once by its owning block).
__device__ float g_part[32 * NV_];

// ---- f32x2 packed helpers (FFMA2 path, PTX-only per SASS_QUICKREF) --------
__device__ __forceinline__ u64 pack2(float lo, float hi) {
    u64 r; asm("mov.b64 %0, {%1, %2};" : "=l"(r) : "f"(lo), "f"(hi)); return r;
}
__device__ __forceinline__ void fma2(u64& d, u64 a, u64 b) {
    asm("fma.rn.f32x2 %0, %1, %2, %0;" : "+l"(d) : "l"(a), "l"(b));
}
__device__ __forceinline__ void unpack2(u64 v, float& lo, float& hi) {
    asm("mov.b64 {%0, %1}, %2;" : "=f"(lo), "=f"(hi) : "l"(v));
}

// digitize (np.digitize semantics) + bin weight lookup. Fast arithmetic
// estimate, then exact +/-1 correction against the f32 linspace boundaries
// b_k = -0.5f + k*STEPF (identical formula to the R1-passing kernel).
__device__ __forceinline__ float binval(float s, const float* __restrict__ binw_s) {
    float t = fmaf(s, INV_STEP, HALF_INV_STEP);
    int d = __float2int_rd(t) + 1;
    d = d < 0 ? 0 : (d > 15 ? 15 : d);
    float bd = -0.5f + (float)d * STEPF;
    if (d < 15 && s >= bd) d++;
    float bdm = -0.5f + (float)(d - 1) * STEPF;
    if (d > 0 && s < bdm) d--;
    return binw_s[d];
}

// ---------------------------------------------------------------------------
// Kernel 1: fused GEMM (sim = E[doc] @ VvT) + digitize + bin lookup +
//           attn-weighted reduction over the 128 token rows of this block
//           -> g_part[blockIdx.y][n].
// Tile: 128(M) x 128(N) x 128(K=full), 256 threads. Each thread: 8x8 scalar
// results held as 4 row-pairs x 8 cols of packed f32x2 accumulators.
// ---------------------------------------------------------------------------
__global__ void __launch_bounds__(256, 1)
k1_gemm(const void* __restrict__ doc_raw,
        const float* __restrict__ attn,
        const float* __restrict__ emb,
        const float* __restrict__ vvt,
        const float* __restrict__ diff,
        const float* __restrict__ start) {
    extern __shared__ float sm[];
    float* As     = sm;                    // [k][m], stride 132 (16B-aligned rows)
    float* Bs     = sm + 128 * 132;        // [k][n], stride 128
    float* attn_s = Bs + 128 * 128;        // 128
    float* binw_s = attn_s + 128;          // 16

    const int tid   = threadIdx.x;
    const int mbase = blockIdx.y * 128;
    const int nbase = blockIdx.x * 128;

    // per-thread dtype sniff (int32 read as int64 -> huge/neg values)
    int is64 = 1;
    {
        const long long* p64 = (const long long*)doc_raw;
        #pragma unroll
        for (int i = 0; i < 4; i++) {
            long long v = p64[i];
            if (v < 0 || v >= 50001LL) is64 = 0;
        }
    }

    if (tid < 128) attn_s[tid] = attn[mbase + tid];
    if (tid == 0) {                         // bin weights: start + cumsum(relu(diff))
        float s0 = start[0], acc = 0.0f;
        for (int i = 0; i < 16; i++) {
            float dv = diff[i];
            acc += (dv > 0.0f) ? dv : 0.0f;
            binw_s[i] = s0 + acc;
        }
    }

    // --- load A (gather + transpose to [k][m]) ---
    {
        const long long* doc64 = (const long long*)doc_raw;
        const int*       doc32 = (const int*)doc_raw;
        const float4* emb4 = (const float4*)emb;
        int rl = tid & 31;
        int kq = tid >> 5;
        #pragma unroll
        for (int it = 0; it < 16; it++) {
            int r   = rl + 32 * (it & 3);
            int kf4 = kq + 8 * (it >> 2);
            long long idx = is64 ? doc64[mbase + r] : (long long)doc32[mbase + r];
            float4 v = emb4[idx * 32 + kf4];
            int kk = kf4 * 4;
            As[(kk + 0) * 132 + r] = v.x;
            As[(kk + 1) * 132 + r] = v.y;
            As[(kk + 2) * 132 + r] = v.z;
            As[(kk + 3) * 132 + r] = v.w;
        }
    }
    // --- load B tile ---
    {
        const float4* vvt4 = (const float4*)vvt;
        float4* Bs4 = (float4*)Bs;
        int n4 = tid & 31;
        int kb = tid >> 5;
        #pragma unroll
        for (int it = 0; it < 16; it++) {
            int k = kb + 8 * it;
            Bs4[k * 32 + n4] = vvt4[(size_t)k * (NV_ / 4) + (nbase >> 2) + n4];
        }
    }
    __syncthreads();

    const int tx = tid & 15;
    const int ty = tid >> 4;

    u64 acc[4][8];                          // [row_pair][col], f32x2 packed
    #pragma unroll
    for (int i = 0; i < 4; i++)
        #pragma unroll
        for (int j = 0; j < 8; j++) acc[i][j] = 0ULL;

    #pragma unroll 4
    for (int k = 0; k < 128; k++) {
        float4 a0 = *(const float4*)&As[k * 132 + ty * 4];
        float4 a1 = *(const float4*)&As[k * 132 + 64 + ty * 4];
        float4 b0 = *(const float4*)&Bs[k * 128 + tx * 4];
        float4 b1 = *(const float4*)&Bs[k * 128 + 64 + tx * 4];
        u64 ap[4] = { pack2(a0.x, a0.y), pack2(a0.z, a0.w),
                      pack2(a1.x, a1.y), pack2(a1.z, a1.w) };
        float bv[8] = { b0.x, b0.y, b0.z, b0.w, b1.x, b1.y, b1.z, b1.w };
        #pragma unroll
        for (int j = 0; j < 8; j++) {
            u64 bb = pack2(bv[j], bv[j]);
            fma2(acc[0][j], ap[0], bb);
            fma2(acc[1][j], ap[1], bb);
            fma2(acc[2][j], ap[2], bb);
            fma2(acc[3][j], ap[3], bb);
        }
    }

    // --- epilogue: unpack, digitize, attn-weighted row partials ---
    float p[8];
    #pragma unroll
    for (int c = 0; c < 8; c++) p[c] = 0.0f;

    #pragma unroll
    for (int rp = 0; rp < 4; rp++) {
        int r_lo = (rp < 2) ? (ty * 4 + rp * 2) : (64 + ty * 4 + (rp - 2) * 2);
        float a_lo = attn_s[r_lo];
        float a_hi = attn_s[r_lo + 1];
        #pragma unroll
        for (int c = 0; c < 8; c++) {
            float s_lo, s_hi;
            unpack2(acc[rp][c], s_lo, s_hi);
            p[c] = fmaf(a_lo, binval(s_lo, binw_s), p[c]);
            p[c] = fmaf(a_hi, binval(s_hi, binw_s), p[c]);
        }
    }

    __syncthreads();            // done reading As; reuse as reduction buffer
    float* red = sm;            // [16][128]
    #pragma unroll
    for (int c = 0; c < 8; c++) {
        int col = (c < 4) ? (tx * 4 + c) : (64 + tx * 4 + (c - 4));
        red[ty * 128 + col] = p[c];
    }
    __syncthreads();
    #pragma unroll
    for (int off = 8; off > 0; off >>= 1) {
        if (ty < off) {
            #pragma unroll
            for (int c = 0; c < 8; c++) {
                int col = (c < 4) ? (tx * 4 + c) : (64 + tx * 4 + (c - 4));
                red[ty * 128 + col] += red[(ty + off) * 128 + col];
            }
        }
        __syncthreads();
    }
    if (ty == 0) {
        #pragma unroll
        for (int c = 0; c < 8; c++) {
            int col = (c < 4) ? (tx * 4 + c) : (64 + tx * 4 + (c - 4));
            g_part[blockIdx.y * NV_ + nbase + col] = red[col];
        }
    }
}

// ---------------------------------------------------------------------------
// Kernel 2: final[b,j] = sum_v (sum_{p=0..3} g_part[b*4+p][v]) * phi[j,v].
// One warp per output; coalesced float4 reads; warp shuffle reduction.
// ---------------------------------------------------------------------------
__global__ void __launch_bounds__(256)
k2_final(const float* __restrict__ phi, float* __restrict__ out) {
    int wid = threadIdx.x >> 5, lane = threadIdx.x & 31;
    int g = blockIdx.x * 8 + wid;      // 0..4095
    int b = g & 7, j = g >> 3;
    const float4* p0 = (const float4*)(g_part + (b * 4 + 0) * NV_);
    const float4* p1 = (const float4*)(g_part + (b * 4 + 1) * NV_);
    const float4* p2 = (const float4*)(g_part + (b * 4 + 2) * NV_);
    const float4* p3 = (const float4*)(g_part + (b * 4 + 3) * NV_);
    const float4* pp = (const float4*)(phi + (size_t)j * NV_);
    float acc = 0.0f;
    #pragma unroll
    for (int i = 0; i < 32; i++) {
        int o = i * 32 + lane;
        float4 v0 = p0[o], v1 = p1[o], v2 = p2[o], v3 = p3[o];
        float4 vp = pp[o];
        float ax = (v0.x + v1.x) + (v2.x + v3.x);
        float ay = (v0.y + v1.y) + (v2.y + v3.y);
        float az = (v0.z + v1.z) + (v2.z + v3.z);
        float aw = (v0.w + v1.w) + (v2.w + v3.w);
        acc = fmaf(ax, vp.x, acc);
        acc = fmaf(ay, vp.y, acc);
        acc = fmaf(az, vp.z, acc);
        acc = fmaf(aw, vp.w, acc);
    }
    #pragma unroll
    for (int off = 16; off > 0; off >>= 1)
        acc += __shfl_xor_sync(0xffffffffu, acc, off);
    if (lane == 0) out[b * NODES_ + j] = acc;
}

// ---------------------------------------------------------------------------
extern "C" void kernel_launch(void* const* d_in, const int* in_sizes, int n_in,
                              void* d_out, int out_size) {
    const void*  doc   = d_in[0];                   // int64 or int32 (sniffed)
    const float* attn  = (const float*)d_in[1];     // [8,512]
    const float* emb   = (const float*)d_in[2];     // [50001,128]
    const float* vvt   = (const float*)d_in[3];     // [128,4096]
    const float* phi   = (const float*)d_in[4];     // [512,4096]
    const float* diff  = (const float*)d_in[5];     // [16]
    const float* start = (const float*)d_in[6];     // [1]
    float* out = (float*)d_out;                     // [8,512] f32

    size_t smem = (size_t)(128 * 132 + 128 * 128 + 128 + 16) * sizeof(float);
    cudaFuncSetAttribute(k1_gemm, cudaFuncAttributeMaxDynamicSharedMemorySize,
                         (int)smem);

    dim3 grid(NV_ / 128, (B_ * ND_) / 128);   // 32 x 32
    k1_gemm<<<grid, 256, smem>>>(doc, attn, emb, vvt, diff, start);
    k2_final<<<(B_ * NODES_) / 8, 256>>>(phi, out);
}

// round 5
// speedup vs baseline: 1.1414x; 1.1414x over previous
#include <cuda_runtime.h>
#include <cuda_bf16.h>
#include <cstdint>

#define NV_    4096
#define B_     8
#define ND_    512
#define NODES_ 512

#define STEPF    ((0.99f - (-0.5f)) / 14.0f)
#define INV_STEP 9.3959731543624161f
#define HALF_INV_STEP 4.6979865771812080f

// Row-major bf16 tile images [4096 rows][128 k] = [4096][16] uint4 (1MB each).
// 3-term splits: a = a0+a1+a2 (each bf16), same for b (VvT columns).
__device__ uint4 g_a0[4096 * 16];
__device__ uint4 g_a1[4096 * 16];
__device__ uint4 g_a2[4096 * 16];
__device__ uint4 g_b0[4096 * 16];
__device__ uint4 g_b1[4096 * 16];
__device__ uint4 g_b2[4096 * 16];
__device__ float g_part[32 * NV_];          // per-m-block partial a
__device__ float g_opart[4 * B_ * NODES_];  // per-v-split partial outputs

// ---------------------------------------------------------------------------
// helpers
// ---------------------------------------------------------------------------
__device__ __forceinline__ uint32_t packbf(float a, float b) {
    __nv_bfloat162 t = __floats2bfloat162_rn(a, b);
    return *reinterpret_cast<uint32_t*>(&t);
}
__device__ __forceinline__ uint32_t smem_u32(const void* p) {
    uint32_t a;
    asm("{ .reg .u64 t; cvta.to.shared.u64 t, %1; cvt.u32.u64 %0, t; }"
        : "=r"(a) : "l"(p));
    return a;
}
__device__ __forceinline__ void cp16(uint32_t dst, const void* src) {
    asm volatile("cp.async.cg.shared.global [%0], [%1], 16;"
                 :: "r"(dst), "l"(src) : "memory");
}
__device__ __forceinline__ void ldm_x4(uint32_t* r, uint32_t a) {
    asm volatile("ldmatrix.sync.aligned.m8n8.x4.shared.b16 {%0,%1,%2,%3}, [%4];"
                 : "=r"(r[0]), "=r"(r[1]), "=r"(r[2]), "=r"(r[3]) : "r"(a));
}
__device__ __forceinline__ void mma16816(float* c, const uint32_t* a,
                                         uint32_t b0, uint32_t b1) {
    asm volatile(
        "mma.sync.aligned.m16n8k16.row.col.f32.bf16.bf16.f32 "
        "{%0,%1,%2,%3}, {%4,%5,%6,%7}, {%8,%9}, {%0,%1,%2,%3};"
        : "+f"(c[0]), "+f"(c[1]), "+f"(c[2]), "+f"(c[3])
        : "r"(a[0]), "r"(a[1]), "r"(a[2]), "r"(a[3]), "r"(b0), "r"(b1));
}

// exact np.digitize vs f32 linspace boundaries b_k = -0.5f + k*STEPF
__device__ __forceinline__ float binval(float s, const float* __restrict__ binw) {
    float t = fmaf(s, INV_STEP, HALF_INV_STEP);
    int d = __float2int_rd(t) + 1;
    d = d < 0 ? 0 : (d > 15 ? 15 : d);
    float bd = -0.5f + (float)d * STEPF;
    if (d < 15 && s >= bd) d++;
    float bdm = -0.5f + (float)(d - 1) * STEPF;
    if (d > 0 && s < bdm) d--;
    return binw[d];
}

// split a float into 3 bf16 terms
__device__ __forceinline__ void split3(float a, float& t0, float& t1, float& t2) {
    t0 = __bfloat162float(__float2bfloat16_rn(a));
    float r = a - t0;
    t1 = __bfloat162float(__float2bfloat16_rn(r));
    t2 = r - t1;                 // rounded to bf16 again at pack time
}

// ---------------------------------------------------------------------------
// k0: gather emb rows / transpose VvT cols, 3-term bf16 split, write
// row-major [4096][128] bf16 images. Threads 0..4095: A. 4096..8191: B.
// ---------------------------------------------------------------------------
__global__ void __launch_bounds__(256)
k0_convert(const void* __restrict__ doc_raw,
           const float* __restrict__ emb,
           const float* __restrict__ vvt) {
    int t = blockIdx.x * blockDim.x + threadIdx.x;    // 0..8191
    const long long* p64 = (const long long*)doc_raw;
    int is64 = 1;
    #pragma unroll
    for (int i = 0; i < 4; i++) {
        long long v = p64[i];
        if (v < 0 || v >= 50001LL) is64 = 0;
    }
    if (t < 4096) {
        long long idx = is64 ? p64[t] : (long long)((const int*)doc_raw)[t];
        const float4* e4 = (const float4*)(emb + idx * 128);
        #pragma unroll 2
        for (int j = 0; j < 16; j++) {
            float4 v0 = e4[j * 2], v1 = e4[j * 2 + 1];
            float f[8] = {v0.x, v0.y, v0.z, v0.w, v1.x, v1.y, v1.z, v1.w};
            uint32_t w0[4], w1[4], w2[4];
            #pragma unroll
            for (int i = 0; i < 4; i++) {
                float x0, x1, x2, y0, y1, y2;
                split3(f[2 * i], x0, x1, x2);
                split3(f[2 * i + 1], y0, y1, y2);
                w0[i] = packbf(x0, y0);
                w1[i] = packbf(x1, y1);
                w2[i] = packbf(x2, y2);
            }
            g_a0[t * 16 + j] = make_uint4(w0[0], w0[1], w0[2], w0[3]);
            g_a1[t * 16 + j] = make_uint4(w1[0], w1[1], w1[2], w1[3]);
            g_a2[t * 16 + j] = make_uint4(w2[0], w2[1], w2[2], w2[3]);
        }
    } else {
        int n = t - 4096;
        #pragma unroll 2
        for (int j = 0; j < 16; j++) {
            float f[8];
            #pragma unroll
            for (int i = 0; i < 8; i++)
                f[i] = vvt[(size_t)(j * 8 + i) * 4096 + n];
            uint32_t w0[4], w1[4], w2[4];
            #pragma unroll
            for (int i = 0; i < 4; i++) {
                float x0, x1, x2, y0, y1, y2;
                split3(f[2 * i], x0, x1, x2);
                split3(f[2 * i + 1], y0, y1, y2);
                w0[i] = packbf(x0, y0);
                w1[i] = packbf(x1, y1);
                w2[i] = packbf(x2, y2);
            }
            g_b0[n * 16 + j] = make_uint4(w0[0], w0[1], w0[2], w0[3]);
            g_b1[n * 16 + j] = make_uint4(w1[0], w1[1], w1[2], w1[3]);
            g_b2[n * 16 + j] = make_uint4(w2[0], w2[1], w2[2], w2[3]);
        }
    }
}

// ---------------------------------------------------------------------------
// k1: HMMA bf16 3-term-split GEMM tile (128x128, K=128; passes a0b0, a0b1,
// a1b0, a1b1, a2b0, a0b2) + fused digitize epilogue.
// 256 threads = 8 warps (4m x 2n), warp tile 32m x 64n.
// SMEM: 6 tile buffers, row stride 272B (conflict-free ldmatrix).
// ---------------------------------------------------------------------------
#define ROWB 272          // bytes per smem row (136 bf16)
#define BUFB (128 * ROWB) // 34816 bytes per buffer
#define SMEM_DYN (6 * BUFB)

__device__ __forceinline__ void run_pass(uint32_t uA, uint32_t uB,
                                         float (*acc)[8][4],
                                         uint32_t a_off, uint32_t b_off) {
    #pragma unroll
    for (int ks = 0; ks < 8; ks++) {
        uint32_t kb = ks * 32;               // bytes: 16 bf16 per k-step
        uint32_t a0[4], a1[4];
        ldm_x4(a0, uA + a_off + kb);
        ldm_x4(a1, uA + a_off + 16 * ROWB + kb);
        #pragma unroll
        for (int nf16 = 0; nf16 < 4; nf16++) {
            uint32_t b[4];
            ldm_x4(b, uB + b_off + nf16 * 16 * ROWB + kb);
            mma16816(acc[0][nf16 * 2],     a0, b[0], b[1]);
            mma16816(acc[0][nf16 * 2 + 1], a0, b[2], b[3]);
            mma16816(acc[1][nf16 * 2],     a1, b[0], b[1]);
            mma16816(acc[1][nf16 * 2 + 1], a1, b[2], b[3]);
        }
    }
}

__global__ void __launch_bounds__(256, 1)
k1_mma(const float* __restrict__ attn,
       const float* __restrict__ diff,
       const float* __restrict__ start) {
    extern __shared__ char dynsm[];
    __shared__ float s_binw[16];
    __shared__ float s_attn[128];
    __shared__ float s_red2[256];

    const int tid  = threadIdx.x;
    const int lane = tid & 31;
    const int wid  = tid >> 5;
    const int warp_m = wid & 3, warp_n = wid >> 2;
    const int nb = blockIdx.x, mb = blockIdx.y;

    const uint32_t uS  = smem_u32(dynsm);
    const uint32_t uA0 = uS;
    const uint32_t uA1 = uS + BUFB;
    const uint32_t uA2 = uS + 2 * BUFB;
    const uint32_t uB0 = uS + 3 * BUFB;
    const uint32_t uB1 = uS + 4 * BUFB;
    const uint32_t uB2 = uS + 5 * BUFB;

    if (tid < 128) s_attn[tid] = attn[mb * 128 + tid];
    if (tid == 0) {
        float s0 = start[0], acc = 0.0f;
        for (int i = 0; i < 16; i++) {
            float dv = diff[i];
            acc += (dv > 0.0f) ? dv : 0.0f;
            s_binw[i] = s0 + acc;
        }
    }

    // async loads: group 1 = a0,a1,b0,b1 ; group 2 = a2,b2
    {
        const uint4* ga0 = g_a0 + mb * 2048;
        const uint4* ga1 = g_a1 + mb * 2048;
        const uint4* gb0 = g_b0 + nb * 2048;
        const uint4* gb1 = g_b1 + nb * 2048;
        #pragma unroll
        for (int c = tid; c < 2048; c += 256) {
            uint32_t d = (uint32_t)(c >> 4) * ROWB + (uint32_t)(c & 15) * 16;
            cp16(uA0 + d, ga0 + c);
            cp16(uA1 + d, ga1 + c);
            cp16(uB0 + d, gb0 + c);
            cp16(uB1 + d, gb1 + c);
        }
        asm volatile("cp.async.commit_group;" ::: "memory");
        const uint4* ga2 = g_a2 + mb * 2048;
        const uint4* gb2 = g_b2 + nb * 2048;
        #pragma unroll
        for (int c = tid; c < 2048; c += 256) {
            uint32_t d = (uint32_t)(c >> 4) * ROWB + (uint32_t)(c & 15) * 16;
            cp16(uA2 + d, ga2 + c);
            cp16(uB2 + d, gb2 + c);
        }
        asm volatile("cp.async.commit_group;" ::: "memory");
    }

    // per-thread ldmatrix lane offsets
    const uint32_t a_off = (uint32_t)(warp_m * 32 + (lane & 15)) * ROWB +
                           (uint32_t)(lane >> 4) * 16;
    const int bn = (lane & 7) + ((lane >> 4) << 3);
    const uint32_t b_off = (uint32_t)(warp_n * 64 + bn) * ROWB +
                           (uint32_t)((lane >> 3) & 1) * 16;

    float acc[2][8][4];
    #pragma unroll
    for (int i = 0; i < 2; i++)
        #pragma unroll
        for (int j = 0; j < 8; j++)
            #pragma unroll
            for (int q = 0; q < 4; q++) acc[i][j][q] = 0.0f;

    asm volatile("cp.async.wait_group 1;" ::: "memory");
    __syncthreads();
    run_pass(uA0, uB0, acc, a_off, b_off);     // a0*b0
    run_pass(uA0, uB1, acc, a_off, b_off);     // a0*b1
    run_pass(uA1, uB0, acc, a_off, b_off);     // a1*b0
    run_pass(uA1, uB1, acc, a_off, b_off);     // a1*b1
    asm volatile("cp.async.wait_group 0;" ::: "memory");
    __syncthreads();
    run_pass(uA2, uB0, acc, a_off, b_off);     // a2*b0
    run_pass(uA0, uB2, acc, a_off, b_off);     // a0*b2

    __syncthreads();   // done reading tile buffers; reuse as red[128][132]

    // ---- epilogue: digitize + attn weight -> red, column reduce ----
    float* red = (float*)dynsm;                  // stride 132 (conflict-free)
    {
        const int r0b = warp_m * 32 + (lane >> 2);
        const int colb = warp_n * 64 + (lane & 3) * 2;
        #pragma unroll
        for (int mf = 0; mf < 2; mf++) {
            int ra = r0b + mf * 16;
            float aa = s_attn[ra], ab = s_attn[ra + 8];
            #pragma unroll
            for (int nf = 0; nf < 8; nf++) {
                int cc = colb + nf * 8;
                float* f = acc[mf][nf];
                red[ra * 132 + cc]           = aa * binval(f[0], s_binw);
                red[ra * 132 + cc + 1]       = aa * binval(f[1], s_binw);
                red[(ra + 8) * 132 + cc]     = ab * binval(f[2], s_binw);
                red[(ra + 8) * 132 + cc + 1] = ab * binval(f[3], s_binw);
            }
        }
    }
    __syncthreads();
    {
        int col = tid & 127, half = tid >> 7;
        float s0 = 0.f, s1 = 0.f;
        #pragma unroll 8
        for (int r = half * 64; r < half * 64 + 64; r += 2) {
            s0 += red[r * 132 + col];
            s1 += red[(r + 1) * 132 + col];
        }
        s_red2[half * 128 + col] = s0 + s1;
    }
    __syncthreads();
    if (tid < 128)
        g_part[mb * NV_ + nb * 128 + tid] = s_red2[tid] + s_red2[128 + tid];
}

// ---------------------------------------------------------------------------
// k2: blocked GEMM out[b,j] = sum_v a[b,v]*phi[j,v]. grid (4 v-splits, 32
// j-tiles of 16). Partials -> g_opart.  k3 combines.
// ---------------------------------------------------------------------------
__global__ void __launch_bounds__(256)
k2_gemm2(const float* __restrict__ phi) {
    __shared__ float asum[8 * 1024];
    const int vs = blockIdx.x, jt = blockIdx.y;
    const int tid = threadIdx.x;
    const int vbase = vs * 1024;

    for (int i = tid; i < 8192; i += 256) {
        int b = i >> 10, v = i & 1023;
        int gv = vbase + v;
        asum[i] = (g_part[(4 * b + 0) * NV_ + gv] + g_part[(4 * b + 1) * NV_ + gv]) +
                  (g_part[(4 * b + 2) * NV_ + gv] + g_part[(4 * b + 3) * NV_ + gv]);
    }
    __syncthreads();

    const int wid = tid >> 5, lane = tid & 31;
    const float4* asum4 = (const float4*)asum;
    #pragma unroll 4
    for (int c = 0; c < 16; c++) {
        int cid = wid * 16 + c;
        int jl = cid >> 3, b = cid & 7;
        int j = jt * 16 + jl;
        const float4* p4 = (const float4*)(phi + (size_t)j * NV_ + vbase);
        float acc = 0.f;
        #pragma unroll
        for (int it = 0; it < 8; it++) {
            float4 a4 = asum4[b * 256 + it * 32 + lane];
            float4 pp = p4[it * 32 + lane];
            acc = fmaf(a4.x, pp.x, acc);
            acc = fmaf(a4.y, pp.y, acc);
            acc = fmaf(a4.z, pp.z, acc);
            acc = fmaf(a4.w, pp.w, acc);
        }
        #pragma unroll
        for (int o = 16; o > 0; o >>= 1)
            acc += __shfl_xor_sync(0xffffffffu, acc, o);
        if (lane == 0) g_opart[vs * 4096 + b * NODES_ + j] = acc;
    }
}

__global__ void __launch_bounds__(256)
k3_combine(float* __restrict__ out) {
    int o = blockIdx.x * 256 + threadIdx.x;        // 0..4095
    out[o] = (g_opart[o] + g_opart[4096 + o]) +
             (g_opart[8192 + o] + g_opart[12288 + o]);
}

// ---------------------------------------------------------------------------
extern "C" void kernel_launch(void* const* d_in, const int* in_sizes, int n_in,
                              void* d_out, int out_size) {
    const void*  doc   = d_in[0];
    const float* attn  = (const float*)d_in[1];
    const float* emb   = (const float*)d_in[2];
    const float* vvt   = (const float*)d_in[3];
    const float* phi   = (const float*)d_in[4];
    const float* diff  = (const float*)d_in[5];
    const float* start = (const float*)d_in[6];
    float* out = (float*)d_out;

    static int smem_set = 0;
    if (!smem_set) {
        cudaFuncSetAttribute(k1_mma, cudaFuncAttributeMaxDynamicSharedMemorySize,
                             SMEM_DYN);
        smem_set = 1;
    }

    k0_convert<<<32, 256>>>(doc, emb, vvt);
    dim3 g1(NV_ / 128, (B_ * ND_) / 128);          // 32 x 32
    k1_mma<<<g1, 256, SMEM_DYN>>>(attn, diff, start);
    dim3 g2(4, 32);
    k2_gemm2<<<g2, 256>>>(phi);
    k3_combine<<<16, 256>>>(out);
}

// round 6
// speedup vs baseline: 1.5431x; 1.3520x over previous
#include <cuda_runtime.h>
#include <cuda_fp16.h>
#include <cstdint>

#define NV_    4096
#define B_     8
#define ND_    512
#define NODES_ 512

#define STEPF    ((0.99f - (-0.5f)) / 14.0f)
#define INV_STEP 9.3959731543624161f
#define HALF_INV_STEP 4.6979865771812080f
#define CORR_SCALE 2.44140625e-4f     // 2^-12

// Row-major fp16 tile images [4096 rows][128 k] = [4096][16] uint4 (1MB each).
// 2-term fp16 split: a = x0 + x1s*2^-12 (x1s stored pre-scaled by 2^12).
__device__ uint4 g_a0[4096 * 16];
__device__ uint4 g_a1[4096 * 16];     // scaled tail
__device__ uint4 g_b0[4096 * 16];
__device__ uint4 g_b1[4096 * 16];     // scaled tail
__device__ float g_part[32 * NV_];
__device__ float g_opart[4 * B_ * NODES_];

// ---------------------------------------------------------------------------
// helpers
// ---------------------------------------------------------------------------
__device__ __forceinline__ uint32_t packhf(float a, float b) {
    __half2 t = __floats2half2_rn(a, b);
    return *reinterpret_cast<uint32_t*>(&t);
}
__device__ __forceinline__ uint32_t smem_u32(const void* p) {
    uint32_t a;
    asm("{ .reg .u64 t; cvta.to.shared.u64 t, %1; cvt.u32.u64 %0, t; }"
        : "=r"(a) : "l"(p));
    return a;
}
__device__ __forceinline__ void cp16(uint32_t dst, const void* src) {
    asm volatile("cp.async.cg.shared.global [%0], [%1], 16;"
                 :: "r"(dst), "l"(src) : "memory");
}
__device__ __forceinline__ void ldm_x4(uint32_t* r, uint32_t a) {
    asm volatile("ldmatrix.sync.aligned.m8n8.x4.shared.b16 {%0,%1,%2,%3}, [%4];"
                 : "=r"(r[0]), "=r"(r[1]), "=r"(r[2]), "=r"(r[3]) : "r"(a));
}
__device__ __forceinline__ void mma16816(float* c, const uint32_t* a,
                                         uint32_t b0, uint32_t b1) {
    asm volatile(
        "mma.sync.aligned.m16n8k16.row.col.f32.f16.f16.f32 "
        "{%0,%1,%2,%3}, {%4,%5,%6,%7}, {%8,%9}, {%0,%1,%2,%3};"
        : "+f"(c[0]), "+f"(c[1]), "+f"(c[2]), "+f"(c[3])
        : "r"(a[0]), "r"(a[1]), "r"(a[2]), "r"(a[3]), "r"(b0), "r"(b1));
}

// exact np.digitize vs f32 linspace boundaries b_k = -0.5f + k*STEPF
__device__ __forceinline__ float binval(float s, const float* __restrict__ binw) {
    float t = fmaf(s, INV_STEP, HALF_INV_STEP);
    int d = __float2int_rd(t) + 1;
    d = d < 0 ? 0 : (d > 15 ? 15 : d);
    float bd = -0.5f + (float)d * STEPF;
    if (d < 15 && s >= bd) d++;
    float bdm = -0.5f + (float)(d - 1) * STEPF;
    if (d > 0 && s < bdm) d--;
    return binw[d];
}

// 2-term fp16 split: a = h0 + h1*2^-12 (+ rho, |rho| <= 2^-24 |a|)
__device__ __forceinline__ void split2(float a, float& h0, float& h1s) {
    h0 = __half2float(__float2half_rn(a));
    float r = a - h0;                      // exact (Sterbenz)
    h1s = r * 4096.0f;                     // exact power-of-2 scale
}

// ---------------------------------------------------------------------------
// k0: gather emb rows / transpose VvT cols, 2-term fp16 split, write
// row-major [4096][128] fp16 images. Threads 0..4095: A. 4096..8191: B.
// ---------------------------------------------------------------------------
__global__ void __launch_bounds__(256)
k0_convert(const void* __restrict__ doc_raw,
           const float* __restrict__ emb,
           const float* __restrict__ vvt) {
    int t = blockIdx.x * blockDim.x + threadIdx.x;    // 0..8191
    const long long* p64 = (const long long*)doc_raw;
    int is64 = 1;
    #pragma unroll
    for (int i = 0; i < 4; i++) {
        long long v = p64[i];
        if (v < 0 || v >= 50001LL) is64 = 0;
    }
    if (t < 4096) {
        long long idx = is64 ? p64[t] : (long long)((const int*)doc_raw)[t];
        const float4* e4 = (const float4*)(emb + idx * 128);
        #pragma unroll 2
        for (int j = 0; j < 16; j++) {
            float4 v0 = e4[j * 2], v1 = e4[j * 2 + 1];
            float f[8] = {v0.x, v0.y, v0.z, v0.w, v1.x, v1.y, v1.z, v1.w};
            uint32_t w0[4], w1[4];
            #pragma unroll
            for (int i = 0; i < 4; i++) {
                float x0, x1, y0, y1;
                split2(f[2 * i], x0, x1);
                split2(f[2 * i + 1], y0, y1);
                w0[i] = packhf(x0, y0);
                w1[i] = packhf(x1, y1);
            }
            g_a0[t * 16 + j] = make_uint4(w0[0], w0[1], w0[2], w0[3]);
            g_a1[t * 16 + j] = make_uint4(w1[0], w1[1], w1[2], w1[3]);
        }
    } else {
        int n = t - 4096;
        #pragma unroll 2
        for (int j = 0; j < 16; j++) {
            float f[8];
            #pragma unroll
            for (int i = 0; i < 8; i++)
                f[i] = vvt[(size_t)(j * 8 + i) * 4096 + n];
            uint32_t w0[4], w1[4];
            #pragma unroll
            for (int i = 0; i < 4; i++) {
                float x0, x1, y0, y1;
                split2(f[2 * i], x0, x1);
                split2(f[2 * i + 1], y0, y1);
                w0[i] = packhf(x0, y0);
                w1[i] = packhf(x1, y1);
            }
            g_b0[n * 16 + j] = make_uint4(w0[0], w0[1], w0[2], w0[3]);
            g_b1[n * 16 + j] = make_uint4(w1[0], w1[1], w1[2], w1[3]);
        }
    }
}

// ---------------------------------------------------------------------------
// k1: HMMA fp16 2-term-split GEMM tile (128x128, K=128; passes x0y0 -> main,
// x0y1s + x1sy0 -> corr) + fused digitize epilogue.
// 256 threads = 8 warps (4m x 2n), warp tile 32m x 64n.
// ---------------------------------------------------------------------------
#define ROWB 272          // bytes per smem row (136 halves)
#define BUFB (128 * ROWB) // 34816 bytes per buffer
#define SMEM_DYN (4 * BUFB)

__device__ __forceinline__ void run_pass(uint32_t uA, uint32_t uB,
                                         float (*acc)[8][4],
                                         uint32_t a_off, uint32_t b_off) {
    #pragma unroll
    for (int ks = 0; ks < 8; ks++) {
        uint32_t kb = ks * 32;               // 16 halves per k-step
        uint32_t a0[4], a1[4];
        ldm_x4(a0, uA + a_off + kb);
        ldm_x4(a1, uA + a_off + 16 * ROWB + kb);
        #pragma unroll
        for (int nf16 = 0; nf16 < 4; nf16++) {
            uint32_t b[4];
            ldm_x4(b, uB + b_off + nf16 * 16 * ROWB + kb);
            mma16816(acc[0][nf16 * 2],     a0, b[0], b[1]);
            mma16816(acc[0][nf16 * 2 + 1], a0, b[2], b[3]);
            mma16816(acc[1][nf16 * 2],     a1, b[0], b[1]);
            mma16816(acc[1][nf16 * 2 + 1], a1, b[2], b[3]);
        }
    }
}

__global__ void __launch_bounds__(256, 1)
k1_mma(const float* __restrict__ attn,
       const float* __restrict__ diff,
       const float* __restrict__ start) {
    extern __shared__ char dynsm[];
    __shared__ float s_binw[16];
    __shared__ float s_attn[128];
    __shared__ float s_red2[256];

    const int tid  = threadIdx.x;
    const int lane = tid & 31;
    const int wid  = tid >> 5;
    const int warp_m = wid & 3, warp_n = wid >> 2;
    const int nb = blockIdx.x, mb = blockIdx.y;

    const uint32_t uS  = smem_u32(dynsm);
    const uint32_t uA0 = uS;
    const uint32_t uB0 = uS + BUFB;
    const uint32_t uA1 = uS + 2 * BUFB;
    const uint32_t uB1 = uS + 3 * BUFB;

    if (tid < 128) s_attn[tid] = attn[mb * 128 + tid];
    if (tid == 0) {
        float s0 = start[0], acc = 0.0f;
        for (int i = 0; i < 16; i++) {
            float dv = diff[i];
            acc += (dv > 0.0f) ? dv : 0.0f;
            s_binw[i] = s0 + acc;
        }
    }

    // async loads: group 1 = x0,y0 ; group 2 = x1s,y1s
    {
        const uint4* ga0 = g_a0 + mb * 2048;
        const uint4* gb0 = g_b0 + nb * 2048;
        #pragma unroll
        for (int c = tid; c < 2048; c += 256) {
            uint32_t d = (uint32_t)(c >> 4) * ROWB + (uint32_t)(c & 15) * 16;
            cp16(uA0 + d, ga0 + c);
            cp16(uB0 + d, gb0 + c);
        }
        asm volatile("cp.async.commit_group;" ::: "memory");
        const uint4* ga1 = g_a1 + mb * 2048;
        const uint4* gb1 = g_b1 + nb * 2048;
        #pragma unroll
        for (int c = tid; c < 2048; c += 256) {
            uint32_t d = (uint32_t)(c >> 4) * ROWB + (uint32_t)(c & 15) * 16;
            cp16(uA1 + d, ga1 + c);
            cp16(uB1 + d, gb1 + c);
        }
        asm volatile("cp.async.commit_group;" ::: "memory");
    }

    // per-thread ldmatrix lane offsets
    const uint32_t a_off = (uint32_t)(warp_m * 32 + (lane & 15)) * ROWB +
                           (uint32_t)(lane >> 4) * 16;
    const int bn = (lane & 7) + ((lane >> 4) << 3);
    const uint32_t b_off = (uint32_t)(warp_n * 64 + bn) * ROWB +
                           (uint32_t)((lane >> 3) & 1) * 16;

    float accm[2][8][4];     // main: x0*y0
    float accc[2][8][4];     // corr: 2^12*(x0*y1 + x1*y0)
    #pragma unroll
    for (int i = 0; i < 2; i++)
        #pragma unroll
        for (int j = 0; j < 8; j++)
            #pragma unroll
            for (int q = 0; q < 4; q++) { accm[i][j][q] = 0.0f; accc[i][j][q] = 0.0f; }

    asm volatile("cp.async.wait_group 1;" ::: "memory");
    __syncthreads();
    run_pass(uA0, uB0, accm, a_off, b_off);      // x0*y0
    asm volatile("cp.async.wait_group 0;" ::: "memory");
    __syncthreads();
    run_pass(uA0, uB1, accc, a_off, b_off);      // x0*y1s
    run_pass(uA1, uB0, accc, a_off, b_off);      // x1s*y0

    __syncthreads();   // done reading tile buffers; reuse as red[128][132]

    // ---- epilogue: combine, digitize + attn weight -> red, column reduce ----
    float* red = (float*)dynsm;                  // stride 132 (conflict-free)
    {
        const int r0b = warp_m * 32 + (lane >> 2);
        const int colb = warp_n * 64 + (lane & 3) * 2;
        #pragma unroll
        for (int mf = 0; mf < 2; mf++) {
            int ra = r0b + mf * 16;
            float aa = s_attn[ra], ab = s_attn[ra + 8];
            #pragma unroll
            for (int nf = 0; nf < 8; nf++) {
                int cc = colb + nf * 8;
                float* fm = accm[mf][nf];
                float* fc = accc[mf][nf];
                float s0v = fmaf(fc[0], CORR_SCALE, fm[0]);
                float s1v = fmaf(fc[1], CORR_SCALE, fm[1]);
                float s2v = fmaf(fc[2], CORR_SCALE, fm[2]);
                float s3v = fmaf(fc[3], CORR_SCALE, fm[3]);
                red[ra * 132 + cc]           = aa * binval(s0v, s_binw);
                red[ra * 132 + cc + 1]       = aa * binval(s1v, s_binw);
                red[(ra + 8) * 132 + cc]     = ab * binval(s2v, s_binw);
                red[(ra + 8) * 132 + cc + 1] = ab * binval(s3v, s_binw);
            }
        }
    }
    __syncthreads();
    {
        int col = tid & 127, half = tid >> 7;
        float s0 = 0.f, s1 = 0.f;
        #pragma unroll 8
        for (int r = half * 64; r < half * 64 + 64; r += 2) {
            s0 += red[r * 132 + col];
            s1 += red[(r + 1) * 132 + col];
        }
        s_red2[half * 128 + col] = s0 + s1;
    }
    __syncthreads();
    if (tid < 128)
        g_part[mb * NV_ + nb * 128 + tid] = s_red2[tid] + s_red2[128 + tid];
}

// ---------------------------------------------------------------------------
// k2: blocked GEMM out[b,j] = sum_v a[b,v]*phi[j,v]. grid (4 v-splits, 32
// j-tiles of 16). Partials -> g_opart.  k3 combines.
// ---------------------------------------------------------------------------
__global__ void __launch_bounds__(256)
k2_gemm2(const float* __restrict__ phi) {
    __shared__ float asum[8 * 1024];
    const int vs = blockIdx.x, jt = blockIdx.y;
    const int tid = threadIdx.x;
    const int vbase = vs * 1024;

    for (int i = tid; i < 8192; i += 256) {
        int b = i >> 10, v = i & 1023;
        int gv = vbase + v;
        asum[i] = (g_part[(4 * b + 0) * NV_ + gv] + g_part[(4 * b + 1) * NV_ + gv]) +
                  (g_part[(4 * b + 2) * NV_ + gv] + g_part[(4 * b + 3) * NV_ + gv]);
    }
    __syncthreads();

    const int wid = tid >> 5, lane = tid & 31;
    const float4* asum4 = (const float4*)asum;
    #pragma unroll 4
    for (int c = 0; c < 16; c++) {
        int cid = wid * 16 + c;
        int jl = cid >> 3, b = cid & 7;
        int j = jt * 16 + jl;
        const float4* p4 = (const float4*)(phi + (size_t)j * NV_ + vbase);
        float acc = 0.f;
        #pragma unroll
        for (int it = 0; it < 8; it++) {
            float4 a4 = asum4[b * 256 + it * 32 + lane];
            float4 pp = p4[it * 32 + lane];
            acc = fmaf(a4.x, pp.x, acc);
            acc = fmaf(a4.y, pp.y, acc);
            acc = fmaf(a4.z, pp.z, acc);
            acc = fmaf(a4.w, pp.w, acc);
        }
        #pragma unroll
        for (int o = 16; o > 0; o >>= 1)
            acc += __shfl_xor_sync(0xffffffffu, acc, o);
        if (lane == 0) g_opart[vs * 4096 + b * NODES_ + j] = acc;
    }
}

__global__ void __launch_bounds__(256)
k3_combine(float* __restrict__ out) {
    int o = blockIdx.x * 256 + threadIdx.x;        // 0..4095
    out[o] = (g_opart[o] + g_opart[4096 + o]) +
             (g_opart[8192 + o] + g_opart[12288 + o]);
}

// ---------------------------------------------------------------------------
extern "C" void kernel_launch(void* const* d_in, const int* in_sizes, int n_in,
                              void* d_out, int out_size) {
    const void*  doc   = d_in[0];
    const float* attn  = (const float*)d_in[1];
    const float* emb   = (const float*)d_in[2];
    const float* vvt   = (const float*)d_in[3];
    const float* phi   = (const float*)d_in[4];
    const float* diff  = (const float*)d_in[5];
    const float* start = (const float*)d_in[6];
    float* out = (float*)d_out;

    static int smem_set = 0;
    if (!smem_set) {
        cudaFuncSetAttribute(k1_mma, cudaFuncAttributeMaxDynamicSharedMemorySize,
                             SMEM_DYN);
        smem_set = 1;
    }

    k0_convert<<<32, 256>>>(doc, emb, vvt);
    dim3 g1(NV_ / 128, (B_ * ND_) / 128);          // 32 x 32
    k1_mma<<<g1, 256, SMEM_DYN>>>(attn, diff, start);
    dim3 g2(4, 32);
    k2_gemm2<<<g2, 256>>>(phi);
    k3_combine<<<16, 256>>>(out);
}